// round 13
// baseline (speedup 1.0000x reference)
#include <cuda_runtime.h>
#include <cuda_fp16.h>
#include <cstdint>

#define E_    8
#define T_    2048
#define H_    2880
#define D_    2880
#define TWOD_ 5760
#define SPLITK 4
#define EPS   (E_ / SPLITK)         // experts per split = 2

#define BM 128
#define BN 128
#define BK 64                       // fp16 k per slab (128B rows, SW128 swizzle)
#define NS 3                        // cp.async stages
#define A_BYTES (BM * BK * 2)       // 16384
#define B_BYTES (BN * BK * 2)       // 16384
#define STAGE_BYTES (A_BYTES + B_BYTES)
#define SMEM_BYTES (NS * STAGE_BYTES)   // 98304 -> 2 CTAs/SM

#define GX1   (T_ / BM)             // 16 gemm1 x-tiles; x == GX1 -> persistent w2-transpose CTA

// ---------------- scratch ----------------
__device__ __align__(1024) __half g_w1t[(size_t)E_ * TWOD_ * H_];  // [e][n][k]
__device__ __align__(1024) __half g_w2t[(size_t)E_ * H_ * D_];     // [e][h][d]
__device__ __align__(1024) __half g_xh[(size_t)T_ * H_];           // [t][k]
__device__ __align__(1024) __half g_hid[(size_t)E_ * T_ * D_];     // [e][t][d]
__device__ __align__(1024) __half g_parth[(size_t)SPLITK * T_ * H_]; // split-k partials (fp16)

// ---------------- PTX helpers (base ISA only) ----------------
__device__ __forceinline__ uint32_t smem_u32(const void* p) {
    uint32_t a;
    asm("{ .reg .u64 t; cvta.to.shared.u64 t, %1; cvt.u32.u64 %0, t; }" : "=r"(a) : "l"(p));
    return a;
}
__device__ __forceinline__ void cpa16(uint32_t dst, const void* src, int sz) {
    asm volatile("cp.async.cg.shared.global [%0], [%1], 16, %2;"
                 :: "r"(dst), "l"(src), "r"(sz) : "memory");
}
#define CP_COMMIT() asm volatile("cp.async.commit_group;" ::: "memory")
#define CP_WAIT(n)  asm volatile("cp.async.wait_group %0;" :: "n"(n) : "memory")

__device__ __forceinline__ void ldsm4(uint32_t (&r)[4], uint32_t addr) {
    asm volatile("ldmatrix.sync.aligned.m8n8.x4.shared.b16 {%0,%1,%2,%3}, [%4];"
                 : "=r"(r[0]), "=r"(r[1]), "=r"(r[2]), "=r"(r[3]) : "r"(addr));
}
__device__ __forceinline__ void mma16816(float c[4], const uint32_t a[4], const uint32_t b[2]) {
    asm volatile("mma.sync.aligned.m16n8k16.row.col.f32.f16.f16.f32 "
                 "{%0,%1,%2,%3}, {%4,%5,%6,%7}, {%8,%9}, {%0,%1,%2,%3};"
                 : "+f"(c[0]), "+f"(c[1]), "+f"(c[2]), "+f"(c[3])
                 : "r"(a[0]), "r"(a[1]), "r"(a[2]), "r"(a[3]), "r"(b[0]), "r"(b[1]));
}

// swizzled address within a [rows][64 halves] tile, 128B rows, Swizzle<3,4,3>
__device__ __forceinline__ uint32_t swaddr(uint32_t base, int row, int colbyte) {
    return base + row * 128 + (colbyte ^ ((row & 7) << 4));
}

// ---------------- prep kernels ----------------
__global__ void k_cvt_half(const float* __restrict__ src) {
    const float2* s2 = (const float2*)src;
    __half2* d2 = (__half2*)g_xh;
    size_t n = (size_t)T_ * H_ / 2;
    for (size_t i = (size_t)blockIdx.x * blockDim.x + threadIdx.x; i < n;
         i += (size_t)gridDim.x * blockDim.x) {
        float2 v = s2[i];
        d2[i] = __floats2half2_rn(v.x, v.y);
    }
}
// dst[z][c][r] = (half)src[z][r][c]; src [Z][R][C]; tiles 64(r) x 32(c)
__global__ void k_transpose_h(const float* __restrict__ src, __half* __restrict__ dst, int R, int C) {
    __shared__ float t[32][65];
    size_t zs = (size_t)blockIdx.z * R * C;
    int r0 = blockIdx.y * 64, c0 = blockIdx.x * 32;
    int tx = threadIdx.x, ty = threadIdx.y;
#pragma unroll
    for (int i = 0; i < 8; i++) {
        int r = ty + i * 8;
        t[tx][r] = src[zs + (size_t)(r0 + r) * C + c0 + tx];
    }
    __syncthreads();
    __half2* d2 = (__half2*)(dst + zs);
#pragma unroll
    for (int j = 0; j < 4; j++) {
        int c = ty + j * 8;
        d2[((size_t)(c0 + c) * R + r0) / 2 + tx] = __floats2half2_rn(t[c][2 * tx], t[c][2 * tx + 1]);
    }
}

// ============================================================================
// Mainloop pieces
// ============================================================================
struct Frag {
    float acc[2][8][4];
};

__device__ __forceinline__ void load_frags(uint32_t sA, uint32_t sB, int kk,
                                           uint32_t (&a)[2][4], uint32_t (&b)[8][2],
                                           int wm, int wn, int lane) {
    const int l7 = lane & 7, l15 = lane & 15;
    const int lb8 = (lane >> 3) & 1, lb16 = (lane >> 4) & 1;
#pragma unroll
    for (int i = 0; i < 2; i++) {
        uint32_t t[4];
        ldsm4(t, swaddr(sA, wm + i * 16 + l15, (kk << 5) | (lb16 << 4)));
        a[i][0] = t[0]; a[i][1] = t[1]; a[i][2] = t[2]; a[i][3] = t[3];
    }
#pragma unroll
    for (int jj = 0; jj < 4; jj++) {
        uint32_t t[4];
        ldsm4(t, swaddr(sB, wn + jj * 16 + l7 + (lb16 << 3), (kk << 5) | (lb8 << 4)));
        b[2 * jj][0] = t[0];     b[2 * jj][1] = t[1];
        b[2 * jj + 1][0] = t[2]; b[2 * jj + 1][1] = t[3];
    }
}

__device__ __forceinline__ void mma_all(Frag& F, const uint32_t (&a)[2][4],
                                        const uint32_t (&b)[8][2]) {
#pragma unroll
    for (int i = 0; i < 2; i++)
#pragma unroll
        for (int j = 0; j < 8; j++)
            mma16816(F.acc[i][j], a[i], b[j]);
}

// ============================================================================
// GEMM1 (fused): x < GX1 -> hid tile; x == GX1 -> persistent w2-transpose CTA
//   360 transpose CTAs (one per (y,z)), each loops 90 tiles; they ride gemm1's
//   idle DRAM pipe and complete before gemm2 launches.
// ============================================================================
__global__ __launch_bounds__(256, 2)
void gemm1_hk(const float* __restrict__ b1, const float* __restrict__ rw,
              const float* __restrict__ w2src) {
    extern __shared__ __align__(1024) char smem[];
    const int tid = threadIdx.x;

    if (blockIdx.x == GX1) {
        // ---- persistent w2 transpose: dst[e][c][r] = (half)src[e][r][c], R=D_, C=H_
        float* t = (float*)smem;                 // [32][65]
        const int cid = blockIdx.z * 45 + blockIdx.y;  // 0..359
        const int tx = tid & 31, ty = tid >> 5;
        for (int it = 0; it < 90; it++) {
            int tile = cid + it * 360;           // 0..32399
            int e = tile / 4050;
            int rem = tile - e * 4050;
            int ry = rem / 90, cx = rem - ry * 90;
            size_t zs = (size_t)e * D_ * H_;
            int r0 = ry * 64, c0 = cx * 32;
#pragma unroll
            for (int i = 0; i < 8; i++) {
                int r = ty + i * 8;
                t[tx * 65 + r] = w2src[zs + (size_t)(r0 + r) * H_ + c0 + tx];
            }
            __syncthreads();
            __half2* d2 = (__half2*)(g_w2t + zs);
#pragma unroll
            for (int j = 0; j < 4; j++) {
                int c = ty + j * 8;
                d2[((size_t)(c0 + c) * D_ + r0) / 2 + tx] =
                    __floats2half2_rn(t[c * 65 + 2 * tx], t[c * 65 + 2 * tx + 1]);
            }
            __syncthreads();
        }
        return;
    }

    const uint32_t sb = smem_u32(smem);
    const int lane = tid & 31, warp = tid >> 5;
    const int wm = (warp & 3) * 32, wn = (warp >> 2) * 64;
    const int m0 = blockIdx.x * BM, n0 = blockIdx.y * BN, e = blockIdx.z;

    Frag F;
#pragma unroll
    for (int i = 0; i < 2; i++)
#pragma unroll
        for (int j = 0; j < 8; j++)
#pragma unroll
            for (int q = 0; q < 4; q++) F.acc[i][j][q] = 0.f;

    const __half* Ab = g_xh + (size_t)m0 * H_;
    const __half* Bb = g_w1t + ((size_t)e * TWOD_ + n0) * H_;
    const int NKT = H_ / BK;  // 45 (divisible by NS=3)

    auto copy_slab = [&](int kt, int buf) {
        uint32_t sA = sb + buf * STAGE_BYTES, sB = sA + A_BYTES;
        const __half* ga = Ab + kt * BK;
        const __half* gb = Bb + kt * BK;
#pragma unroll
        for (int it = 0; it < 4; it++) {
            int ch = tid + it * 256;
            int r = ch >> 3, kc = ch & 7;
            cpa16(swaddr(sA, r, kc * 16), ga + (size_t)r * H_ + kc * 8, 16);
        }
#pragma unroll
        for (int it = 0; it < 4; it++) {
            int ch = tid + it * 256;
            int r = ch >> 3, kc = ch & 7;
            cpa16(swaddr(sB, r, kc * 16), gb + (size_t)r * H_ + kc * 8, 16);
        }
    };

    auto slab_body = [&](int kt, int buf) {
        CP_WAIT(1);
        __syncthreads();
        uint32_t sA = sb + buf * STAGE_BYTES, sB = sA + A_BYTES;
        uint32_t a[2][4], b[8][2];
        load_frags(sA, sB, 0, a, b, wm, wn, lane);
        int nk = kt + 2 < NKT ? kt + 2 : NKT - 1;   // clamped: dead-stage rewrite at tail
        int nb = buf + 2 >= NS ? buf + 2 - NS : buf + 2;
        copy_slab(nk, nb);
        CP_COMMIT();
        mma_all(F, a, b);
#pragma unroll
        for (int kk = 1; kk < BK / 16; kk++) {
            load_frags(sA, sB, kk, a, b, wm, wn, lane);
            mma_all(F, a, b);
        }
    };

    copy_slab(0, 0); CP_COMMIT();
    copy_slab(1, 1); CP_COMMIT();
    for (int kt = 0; kt < NKT; kt += 3) {
        slab_body(kt, 0);
        slab_body(kt + 1, 1);
        slab_body(kt + 2, 2);
    }
    CP_WAIT(0);
    __syncthreads();

    // bias tile -> smem [0, 512)
    float* bsm = (float*)smem;
    for (int i = tid; i < BN; i += 256) bsm[i] = b1[(size_t)e * TWOD_ + n0 + i];
    __syncthreads();

    // activation -> smem bounce tile (padded 72-half rows), then 16B global stores
    const int tig = lane & 3, gid = lane >> 2;
    __half* hsm = (__half*)(smem + 1024);   // [128 rows][72 halves] = 18432B
#pragma unroll
    for (int i = 0; i < 2; i++) {
#pragma unroll
        for (int s = 0; s < 2; s++) {
            int rl = wm + i * 16 + s * 8 + gid;     // local row 0..127
            float rwv = rw[(size_t)(m0 + rl) * E_ + e];
#pragma unroll
            for (int j = 0; j < 8; j++) {
                int cl = wn + j * 8 + 2 * tig;
                float g = F.acc[i][j][2 * s]     + bsm[cl];
                float u = F.acc[i][j][2 * s + 1] + bsm[cl + 1];
                g = fminf(g, 7.0f);
                u = fminf(fmaxf(u, -7.0f), 7.0f);
                float sig = 1.0f / (1.0f + __expf(-1.702f * g));
                hsm[rl * 72 + (cl >> 1)] = __float2half_rn(rwv * (u + 1.0f) * (g * sig));
            }
        }
    }
    __syncthreads();
    {
        int rl = tid >> 1, sel = tid & 1;           // 2 threads per row, 64B each
        const uint4* srcv = (const uint4*)(hsm + rl * 72 + sel * 32);
        uint4 v0 = srcv[0], v1 = srcv[1], v2 = srcv[2], v3 = srcv[3];
        uint4* dst = (uint4*)(g_hid + ((size_t)e * T_ + m0 + rl) * D_ + (n0 >> 1) + sel * 32);
        dst[0] = v0; dst[1] = v1; dst[2] = v2; dst[3] = v3;
    }
}

// ============================================================================
// GEMM2 (split-K over experts): g_parth[z][t,h] = fp16(sum_{e in split z} hid@W2t)
//   epilogue bounced through smem for 16B sector-perfect stores
// ============================================================================
__global__ __launch_bounds__(256, 2)
void gemm2_hk() {
    extern __shared__ __align__(1024) char smem[];
    const uint32_t sb = smem_u32(smem);
    const int tid = threadIdx.x, lane = tid & 31, warp = tid >> 5;
    const int wm = (warp & 3) * 32, wn = (warp >> 2) * 64;
    const int m0 = blockIdx.x * BM, n0 = blockIdx.y * BN, z = blockIdx.z;

    Frag F;
#pragma unroll
    for (int i = 0; i < 2; i++)
#pragma unroll
        for (int j = 0; j < 8; j++)
#pragma unroll
            for (int q = 0; q < 4; q++) F.acc[i][j][q] = 0.f;

    const int KPE = D_ / BK;        // 45
    const int NKT = EPS * KPE;      // 90 (divisible by NS=3)

    auto copy_slab = [&](int kt, int buf) {
        int e = z * EPS + kt / KPE, kin = kt % KPE;
        uint32_t sA = sb + buf * STAGE_BYTES, sB = sA + A_BYTES;
        const __half* ga = g_hid + ((size_t)e * T_ + m0) * D_ + kin * BK;
        const __half* gb = g_w2t + ((size_t)e * H_ + n0) * D_ + kin * BK;
#pragma unroll
        for (int it = 0; it < 4; it++) {
            int ch = tid + it * 256;
            int r = ch >> 3, kc = ch & 7;
            cpa16(swaddr(sA, r, kc * 16), ga + (size_t)r * D_ + kc * 8, 16);
        }
#pragma unroll
        for (int it = 0; it < 4; it++) {
            int ch = tid + it * 256;
            int r = ch >> 3, kc = ch & 7;
            int ok = (n0 + r < H_) ? 16 : 0;     // tail rows zero-filled
            cpa16(swaddr(sB, r, kc * 16), gb + (size_t)r * D_ + kc * 8, ok);
        }
    };

    auto slab_body = [&](int kt, int buf) {
        CP_WAIT(1);
        __syncthreads();
        uint32_t sA = sb + buf * STAGE_BYTES, sB = sA + A_BYTES;
        uint32_t a[2][4], b[8][2];
        load_frags(sA, sB, 0, a, b, wm, wn, lane);
        int nk = kt + 2 < NKT ? kt + 2 : NKT - 1;
        int nb = buf + 2 >= NS ? buf + 2 - NS : buf + 2;
        copy_slab(nk, nb);
        CP_COMMIT();
        mma_all(F, a, b);
#pragma unroll
        for (int kk = 1; kk < BK / 16; kk++) {
            load_frags(sA, sB, kk, a, b, wm, wn, lane);
            mma_all(F, a, b);
        }
    };

    copy_slab(0, 0); CP_COMMIT();
    copy_slab(1, 1); CP_COMMIT();
    for (int kt = 0; kt < NKT; kt += 3) {
        slab_body(kt, 0);
        slab_body(kt + 1, 1);
        slab_body(kt + 2, 2);
    }
    CP_WAIT(0);
    __syncthreads();

    // bounce: fp16 partial tile [128 rows][136 halves] (pad -> conflict-free STS)
    const int tig = lane & 3, gid = lane >> 2;
    __half* psm = (__half*)smem;   // 34816 B
#pragma unroll
    for (int i = 0; i < 2; i++) {
#pragma unroll
        for (int s = 0; s < 2; s++) {
            int rl = wm + i * 16 + s * 8 + gid;
#pragma unroll
            for (int j = 0; j < 8; j++) {
                int cl = wn + j * 8 + 2 * tig;
                __half2 v = __floats2half2_rn(F.acc[i][j][2 * s], F.acc[i][j][2 * s + 1]);
                *(__half2*)(psm + rl * 136 + cl) = v;
            }
        }
    }
    __syncthreads();
    {
        int rl = tid >> 1, sel = tid & 1;           // 2 threads per row, 128B each
        if (n0 + sel * 64 < H_) {
            const uint4* srcv = (const uint4*)(psm + rl * 136 + sel * 64);
            uint4 v[8];
#pragma unroll
            for (int q = 0; q < 8; q++) v[q] = srcv[q];
            uint4* dst = (uint4*)(g_parth + ((size_t)z * T_ + m0 + rl) * H_ + n0 + sel * 64);
#pragma unroll
            for (int q = 0; q < 8; q++) dst[q] = v[q];
        }
    }
}

// ============================================================================
// Reduce: out = sum_z fp16 g_parth[z] + sum_e rw[t,e]*b2[e,h]   (8 cols/thread)
// ============================================================================
__global__ __launch_bounds__(256)
void k_reduce(const float* __restrict__ rw, const float* __restrict__ b2,
              float* __restrict__ out) {
    size_t i8 = (size_t)blockIdx.x * blockDim.x + threadIdx.x;   // uint4 (8-half) index
    const size_t N8 = (size_t)T_ * H_ / 8;
    if (i8 >= N8) return;
    size_t idx = i8 * 8;
    int t = (int)(idx / H_), h = (int)(idx % H_);   // H_%8==0 -> same row

    float acc[8];
#pragma unroll
    for (int q = 0; q < 8; q++) acc[q] = 0.f;
    const uint4* ph = (const uint4*)g_parth;
#pragma unroll
    for (int zz = 0; zz < SPLITK; zz++) {
        uint4 v = ph[(size_t)zz * N8 + i8];
        uint32_t w[4] = {v.x, v.y, v.z, v.w};
#pragma unroll
        for (int q = 0; q < 4; q++) {
            float2 f = __half22float2(*(const __half2*)&w[q]);
            acc[2 * q]     += f.x;
            acc[2 * q + 1] += f.y;
        }
    }

    const float4* rp = (const float4*)(rw + (size_t)t * E_);
    float4 r0 = rp[0], r1 = rp[1];
    float rr[E_] = {r0.x, r0.y, r0.z, r0.w, r1.x, r1.y, r1.z, r1.w};
#pragma unroll
    for (int e = 0; e < E_; e++) {
        const float4* bb = (const float4*)(b2 + (size_t)e * H_ + h);
        float4 b0 = bb[0], b1v = bb[1];
        acc[0] += rr[e] * b0.x;  acc[1] += rr[e] * b0.y;
        acc[2] += rr[e] * b0.z;  acc[3] += rr[e] * b0.w;
        acc[4] += rr[e] * b1v.x; acc[5] += rr[e] * b1v.y;
        acc[6] += rr[e] * b1v.z; acc[7] += rr[e] * b1v.w;
    }
    float4* od = (float4*)(out + idx);
    od[0] = make_float4(acc[0], acc[1], acc[2], acc[3]);
    od[1] = make_float4(acc[4], acc[5], acc[6], acc[7]);
}

// ---------------- host ----------------
extern "C" void kernel_launch(void* const* d_in, const int* in_sizes, int n_in,
                              void* d_out, int out_size) {
    (void)in_sizes; (void)n_in; (void)out_size;
    const float* x  = (const float*)d_in[0];
    const float* rw = (const float*)d_in[1];
    const float* w1 = (const float*)d_in[2];
    const float* b1 = (const float*)d_in[3];
    const float* w2 = (const float*)d_in[4];
    const float* b2 = (const float*)d_in[5];
    float* out = (float*)d_out;

    void *p_w1t;
    cudaGetSymbolAddress(&p_w1t, g_w1t);

    cudaFuncSetAttribute(gemm1_hk, cudaFuncAttributeMaxDynamicSharedMemorySize, SMEM_BYTES);
    cudaFuncSetAttribute(gemm2_hk, cudaFuncAttributeMaxDynamicSharedMemorySize, SMEM_BYTES);

    k_cvt_half<<<2048, 256>>>(x);
    k_transpose_h<<<dim3(TWOD_ / 32, H_ / 64, E_), dim3(32, 8)>>>(w1, (__half*)p_w1t, H_, TWOD_);

    // fused: gemm1 tiles (x<16) + 360 persistent w2-transpose CTAs (x==16)
    gemm1_hk<<<dim3(GX1 + 1, TWOD_ / BN, E_), 256, SMEM_BYTES>>>(b1, rw, w2);
    gemm2_hk<<<dim3(T_ / BM, (H_ + BN - 1) / BN, SPLITK), 256, SMEM_BYTES>>>();
    k_reduce<<<(int)((size_t)T_ * H_ / 8 / 256), 256>>>(rw, b2, out);
}

// round 14
// speedup vs baseline: 1.0370x; 1.0370x over previous
#include <cuda_runtime.h>
#include <cuda_fp16.h>
#include <cstdint>

#define E_    8
#define T_    2048
#define H_    2880
#define D_    2880
#define TWOD_ 5760
#define SPLITK 4
#define EPS   (E_ / SPLITK)         // experts per split = 2

#define BM 128
#define BN 128
#define BK 64                       // fp16 k per slab (128B rows, SW128 swizzle)
#define NS 3                        // cp.async stages
#define A_BYTES (BM * BK * 2)       // 16384
#define B_BYTES (BN * BK * 2)       // 16384
#define STAGE_BYTES (A_BYTES + B_BYTES)
#define SMEM_BYTES (NS * STAGE_BYTES)   // 98304 -> 2 CTAs/SM

// ---------------- scratch ----------------
__device__ __align__(1024) __half g_w1t[(size_t)E_ * TWOD_ * H_];  // [e][n][k]
__device__ __align__(1024) __half g_w2t[(size_t)E_ * H_ * D_];     // [e][h][d]
__device__ __align__(1024) __half g_xh[(size_t)T_ * H_];           // [t][k]
__device__ __align__(1024) __half g_hid[(size_t)E_ * T_ * D_];     // [e][t][d]
__device__ __align__(1024) __half g_parth[(size_t)SPLITK * T_ * H_]; // split-k partials (fp16)

// ---------------- PTX helpers (base ISA only) ----------------
__device__ __forceinline__ uint32_t smem_u32(const void* p) {
    uint32_t a;
    asm("{ .reg .u64 t; cvta.to.shared.u64 t, %1; cvt.u32.u64 %0, t; }" : "=r"(a) : "l"(p));
    return a;
}
__device__ __forceinline__ void cpa16(uint32_t dst, const void* src, int sz) {
    asm volatile("cp.async.cg.shared.global [%0], [%1], 16, %2;"
                 :: "r"(dst), "l"(src), "r"(sz) : "memory");
}
#define CP_COMMIT() asm volatile("cp.async.commit_group;" ::: "memory")
#define CP_WAIT(n)  asm volatile("cp.async.wait_group %0;" :: "n"(n) : "memory")

__device__ __forceinline__ void ldsm4(uint32_t (&r)[4], uint32_t addr) {
    asm volatile("ldmatrix.sync.aligned.m8n8.x4.shared.b16 {%0,%1,%2,%3}, [%4];"
                 : "=r"(r[0]), "=r"(r[1]), "=r"(r[2]), "=r"(r[3]) : "r"(addr));
}
__device__ __forceinline__ void mma16816(float c[4], const uint32_t a[4], const uint32_t b[2]) {
    asm volatile("mma.sync.aligned.m16n8k16.row.col.f32.f16.f16.f32 "
                 "{%0,%1,%2,%3}, {%4,%5,%6,%7}, {%8,%9}, {%0,%1,%2,%3};"
                 : "+f"(c[0]), "+f"(c[1]), "+f"(c[2]), "+f"(c[3])
                 : "r"(a[0]), "r"(a[1]), "r"(a[2]), "r"(a[3]), "r"(b[0]), "r"(b[1]));
}

// swizzled address within a [rows][64 halves] tile, 128B rows, Swizzle<3,4,3>
__device__ __forceinline__ uint32_t swaddr(uint32_t base, int row, int colbyte) {
    return base + row * 128 + (colbyte ^ ((row & 7) << 4));
}

// ---------------- prep kernels ----------------
__global__ void k_cvt_half(const float* __restrict__ src) {
    const float2* s2 = (const float2*)src;
    __half2* d2 = (__half2*)g_xh;
    size_t n = (size_t)T_ * H_ / 2;
    for (size_t i = (size_t)blockIdx.x * blockDim.x + threadIdx.x; i < n;
         i += (size_t)gridDim.x * blockDim.x) {
        float2 v = s2[i];
        d2[i] = __floats2half2_rn(v.x, v.y);
    }
}
// dst[z][c][r] = (half)src[z][r][c]; src [Z][R][C]; tiles 64(r) x 32(c)
__global__ void k_transpose_h(const float* __restrict__ src, __half* __restrict__ dst, int R, int C) {
    __shared__ float t[32][65];
    size_t zs = (size_t)blockIdx.z * R * C;
    int r0 = blockIdx.y * 64, c0 = blockIdx.x * 32;
    int tx = threadIdx.x, ty = threadIdx.y;
#pragma unroll
    for (int i = 0; i < 8; i++) {
        int r = ty + i * 8;
        t[tx][r] = src[zs + (size_t)(r0 + r) * C + c0 + tx];
    }
    __syncthreads();
    __half2* d2 = (__half2*)(dst + zs);
#pragma unroll
    for (int j = 0; j < 4; j++) {
        int c = ty + j * 8;
        d2[((size_t)(c0 + c) * R + r0) / 2 + tx] = __floats2half2_rn(t[c][2 * tx], t[c][2 * tx + 1]);
    }
}

// ============================================================================
// Mainloop pieces
// ============================================================================
struct Frag {
    float acc[2][8][4];
};

__device__ __forceinline__ void load_frags(uint32_t sA, uint32_t sB, int kk,
                                           uint32_t (&a)[2][4], uint32_t (&b)[8][2],
                                           int wm, int wn, int lane) {
    const int l7 = lane & 7, l15 = lane & 15;
    const int lb8 = (lane >> 3) & 1, lb16 = (lane >> 4) & 1;
#pragma unroll
    for (int i = 0; i < 2; i++) {
        uint32_t t[4];
        ldsm4(t, swaddr(sA, wm + i * 16 + l15, (kk << 5) | (lb16 << 4)));
        a[i][0] = t[0]; a[i][1] = t[1]; a[i][2] = t[2]; a[i][3] = t[3];
    }
#pragma unroll
    for (int jj = 0; jj < 4; jj++) {
        uint32_t t[4];
        ldsm4(t, swaddr(sB, wn + jj * 16 + l7 + (lb16 << 3), (kk << 5) | (lb8 << 4)));
        b[2 * jj][0] = t[0];     b[2 * jj][1] = t[1];
        b[2 * jj + 1][0] = t[2]; b[2 * jj + 1][1] = t[3];
    }
}

__device__ __forceinline__ void mma_all(Frag& F, const uint32_t (&a)[2][4],
                                        const uint32_t (&b)[8][2]) {
#pragma unroll
    for (int i = 0; i < 2; i++)
#pragma unroll
        for (int j = 0; j < 8; j++)
            mma16816(F.acc[i][j], a[i], b[j]);
}

// ============================================================================
// GEMM1: hid[e,t,d] = rw[t,e] * glu(X @ W1[e] + b1[e])
// ============================================================================
__global__ __launch_bounds__(256, 2)
void gemm1_hk(const float* __restrict__ b1, const float* __restrict__ rw) {
    extern __shared__ __align__(1024) char smem[];
    const uint32_t sb = smem_u32(smem);
    const int tid = threadIdx.x, lane = tid & 31, warp = tid >> 5;
    const int wm = (warp & 3) * 32, wn = (warp >> 2) * 64;
    const int m0 = blockIdx.x * BM, n0 = blockIdx.y * BN, e = blockIdx.z;

    Frag F;
#pragma unroll
    for (int i = 0; i < 2; i++)
#pragma unroll
        for (int j = 0; j < 8; j++)
#pragma unroll
            for (int q = 0; q < 4; q++) F.acc[i][j][q] = 0.f;

    const __half* Ab = g_xh + (size_t)m0 * H_;
    const __half* Bb = g_w1t + ((size_t)e * TWOD_ + n0) * H_;
    const int NKT = H_ / BK;  // 45 (divisible by NS=3)

    auto copy_slab = [&](int kt, int buf) {
        uint32_t sA = sb + buf * STAGE_BYTES, sB = sA + A_BYTES;
        const __half* ga = Ab + kt * BK;
        const __half* gb = Bb + kt * BK;
#pragma unroll
        for (int it = 0; it < 4; it++) {
            int ch = tid + it * 256;
            int r = ch >> 3, kc = ch & 7;
            cpa16(swaddr(sA, r, kc * 16), ga + (size_t)r * H_ + kc * 8, 16);
        }
#pragma unroll
        for (int it = 0; it < 4; it++) {
            int ch = tid + it * 256;
            int r = ch >> 3, kc = ch & 7;
            cpa16(swaddr(sB, r, kc * 16), gb + (size_t)r * H_ + kc * 8, 16);
        }
    };

    // branch-free slab body: frag(kk0) first, copy-issue under its latency
    auto slab_body = [&](int kt, int buf) {
        CP_WAIT(1);
        __syncthreads();
        uint32_t sA = sb + buf * STAGE_BYTES, sB = sA + A_BYTES;
        uint32_t a[2][4], b[8][2];
        load_frags(sA, sB, 0, a, b, wm, wn, lane);
        int nk = kt + 2 < NKT ? kt + 2 : NKT - 1;   // clamped: dead-stage rewrite at tail
        int nb = buf + 2 >= NS ? buf + 2 - NS : buf + 2;
        copy_slab(nk, nb);
        CP_COMMIT();
        mma_all(F, a, b);
#pragma unroll
        for (int kk = 1; kk < BK / 16; kk++) {
            load_frags(sA, sB, kk, a, b, wm, wn, lane);
            mma_all(F, a, b);
        }
    };

    copy_slab(0, 0); CP_COMMIT();
    copy_slab(1, 1); CP_COMMIT();
    for (int kt = 0; kt < NKT; kt += 3) {
        slab_body(kt, 0);
        slab_body(kt + 1, 1);
        slab_body(kt + 2, 2);
    }
    CP_WAIT(0);
    __syncthreads();

    // bias tile -> smem [0, 512)
    float* bsm = (float*)smem;
    for (int i = tid; i < BN; i += 256) bsm[i] = b1[(size_t)e * TWOD_ + n0 + i];
    __syncthreads();

    // activation -> smem bounce tile (padded 72-half rows), then 16B global stores
    const int tig = lane & 3, gid = lane >> 2;
    __half* hsm = (__half*)(smem + 1024);   // [128 rows][72 halves] = 18432B
#pragma unroll
    for (int i = 0; i < 2; i++) {
#pragma unroll
        for (int s = 0; s < 2; s++) {
            int rl = wm + i * 16 + s * 8 + gid;     // local row 0..127
            float rwv = rw[(size_t)(m0 + rl) * E_ + e];
#pragma unroll
            for (int j = 0; j < 8; j++) {
                int cl = wn + j * 8 + 2 * tig;
                float g = F.acc[i][j][2 * s]     + bsm[cl];
                float u = F.acc[i][j][2 * s + 1] + bsm[cl + 1];
                g = fminf(g, 7.0f);
                u = fminf(fmaxf(u, -7.0f), 7.0f);
                float sig = 1.0f / (1.0f + __expf(-1.702f * g));
                hsm[rl * 72 + (cl >> 1)] = __float2half_rn(rwv * (u + 1.0f) * (g * sig));
            }
        }
    }
    __syncthreads();
    {
        int rl = tid >> 1, sel = tid & 1;           // 2 threads per row, 64B each
        const uint4* srcv = (const uint4*)(hsm + rl * 72 + sel * 32);
        uint4 v0 = srcv[0], v1 = srcv[1], v2 = srcv[2], v3 = srcv[3];
        uint4* dst = (uint4*)(g_hid + ((size_t)e * T_ + m0 + rl) * D_ + (n0 >> 1) + sel * 32);
        dst[0] = v0; dst[1] = v1; dst[2] = v2; dst[3] = v3;
    }
}

// ============================================================================
// GEMM2 (split-K over experts): g_parth[z][t,h] = fp16(sum_{e in split z} hid@W2t)
//   epilogue bounced through smem for 16B sector-perfect stores
// ============================================================================
__global__ __launch_bounds__(256, 2)
void gemm2_hk() {
    extern __shared__ __align__(1024) char smem[];
    const uint32_t sb = smem_u32(smem);
    const int tid = threadIdx.x, lane = tid & 31, warp = tid >> 5;
    const int wm = (warp & 3) * 32, wn = (warp >> 2) * 64;
    const int m0 = blockIdx.x * BM, n0 = blockIdx.y * BN, z = blockIdx.z;

    Frag F;
#pragma unroll
    for (int i = 0; i < 2; i++)
#pragma unroll
        for (int j = 0; j < 8; j++)
#pragma unroll
            for (int q = 0; q < 4; q++) F.acc[i][j][q] = 0.f;

    const int KPE = D_ / BK;        // 45
    const int NKT = EPS * KPE;      // 90 (divisible by NS=3)

    auto copy_slab = [&](int kt, int buf) {
        int e = z * EPS + kt / KPE, kin = kt % KPE;
        uint32_t sA = sb + buf * STAGE_BYTES, sB = sA + A_BYTES;
        const __half* ga = g_hid + ((size_t)e * T_ + m0) * D_ + kin * BK;
        const __half* gb = g_w2t + ((size_t)e * H_ + n0) * D_ + kin * BK;
#pragma unroll
        for (int it = 0; it < 4; it++) {
            int ch = tid + it * 256;
            int r = ch >> 3, kc = ch & 7;
            cpa16(swaddr(sA, r, kc * 16), ga + (size_t)r * D_ + kc * 8, 16);
        }
#pragma unroll
        for (int it = 0; it < 4; it++) {
            int ch = tid + it * 256;
            int r = ch >> 3, kc = ch & 7;
            int ok = (n0 + r < H_) ? 16 : 0;     // tail rows zero-filled
            cpa16(swaddr(sB, r, kc * 16), gb + (size_t)r * D_ + kc * 8, ok);
        }
    };

    auto slab_body = [&](int kt, int buf) {
        CP_WAIT(1);
        __syncthreads();
        uint32_t sA = sb + buf * STAGE_BYTES, sB = sA + A_BYTES;
        uint32_t a[2][4], b[8][2];
        load_frags(sA, sB, 0, a, b, wm, wn, lane);
        int nk = kt + 2 < NKT ? kt + 2 : NKT - 1;
        int nb = buf + 2 >= NS ? buf + 2 - NS : buf + 2;
        copy_slab(nk, nb);
        CP_COMMIT();
        mma_all(F, a, b);
#pragma unroll
        for (int kk = 1; kk < BK / 16; kk++) {
            load_frags(sA, sB, kk, a, b, wm, wn, lane);
            mma_all(F, a, b);
        }
    };

    copy_slab(0, 0); CP_COMMIT();
    copy_slab(1, 1); CP_COMMIT();
    for (int kt = 0; kt < NKT; kt += 3) {
        slab_body(kt, 0);
        slab_body(kt + 1, 1);
        slab_body(kt + 2, 2);
    }
    CP_WAIT(0);
    __syncthreads();

    // bounce: fp16 partial tile [128 rows][136 halves] (pad -> conflict-free STS)
    const int tig = lane & 3, gid = lane >> 2;
    __half* psm = (__half*)smem;   // 34816 B
#pragma unroll
    for (int i = 0; i < 2; i++) {
#pragma unroll
        for (int s = 0; s < 2; s++) {
            int rl = wm + i * 16 + s * 8 + gid;
#pragma unroll
            for (int j = 0; j < 8; j++) {
                int cl = wn + j * 8 + 2 * tig;
                __half2 v = __floats2half2_rn(F.acc[i][j][2 * s], F.acc[i][j][2 * s + 1]);
                *(__half2*)(psm + rl * 136 + cl) = v;
            }
        }
    }
    __syncthreads();
    {
        int rl = tid >> 1, sel = tid & 1;           // 2 threads per row, 128B each
        if (n0 + sel * 64 < H_) {
            const uint4* srcv = (const uint4*)(psm + rl * 136 + sel * 64);
            uint4 v[8];
#pragma unroll
            for (int q = 0; q < 8; q++) v[q] = srcv[q];
            uint4* dst = (uint4*)(g_parth + ((size_t)z * T_ + m0 + rl) * H_ + n0 + sel * 64);
#pragma unroll
            for (int q = 0; q < 8; q++) dst[q] = v[q];
        }
    }
}

// ============================================================================
// Reduce: out = sum_z fp16 g_parth[z] + sum_e rw[t,e]*b2[e,h]   (8 cols/thread)
// ============================================================================
__global__ __launch_bounds__(256)
void k_reduce(const float* __restrict__ rw, const float* __restrict__ b2,
              float* __restrict__ out) {
    size_t i8 = (size_t)blockIdx.x * blockDim.x + threadIdx.x;   // uint4 (8-half) index
    const size_t N8 = (size_t)T_ * H_ / 8;
    if (i8 >= N8) return;
    size_t idx = i8 * 8;
    int t = (int)(idx / H_), h = (int)(idx % H_);   // H_%8==0 -> same row

    float acc[8];
#pragma unroll
    for (int q = 0; q < 8; q++) acc[q] = 0.f;
    const uint4* ph = (const uint4*)g_parth;
#pragma unroll
    for (int zz = 0; zz < SPLITK; zz++) {
        uint4 v = ph[(size_t)zz * N8 + i8];
        uint32_t w[4] = {v.x, v.y, v.z, v.w};
#pragma unroll
        for (int q = 0; q < 4; q++) {
            float2 f = __half22float2(*(const __half2*)&w[q]);
            acc[2 * q]     += f.x;
            acc[2 * q + 1] += f.y;
        }
    }

    const float4* rp = (const float4*)(rw + (size_t)t * E_);
    float4 r0 = rp[0], r1 = rp[1];
    float rr[E_] = {r0.x, r0.y, r0.z, r0.w, r1.x, r1.y, r1.z, r1.w};
#pragma unroll
    for (int e = 0; e < E_; e++) {
        const float4* bb = (const float4*)(b2 + (size_t)e * H_ + h);
        float4 b0 = bb[0], b1v = bb[1];
        acc[0] += rr[e] * b0.x;  acc[1] += rr[e] * b0.y;
        acc[2] += rr[e] * b0.z;  acc[3] += rr[e] * b0.w;
        acc[4] += rr[e] * b1v.x; acc[5] += rr[e] * b1v.y;
        acc[6] += rr[e] * b1v.z; acc[7] += rr[e] * b1v.w;
    }
    float4* od = (float4*)(out + idx);
    od[0] = make_float4(acc[0], acc[1], acc[2], acc[3]);
    od[1] = make_float4(acc[4], acc[5], acc[6], acc[7]);
}

// ---------------- host ----------------
extern "C" void kernel_launch(void* const* d_in, const int* in_sizes, int n_in,
                              void* d_out, int out_size) {
    (void)in_sizes; (void)n_in; (void)out_size;
    const float* x  = (const float*)d_in[0];
    const float* rw = (const float*)d_in[1];
    const float* w1 = (const float*)d_in[2];
    const float* b1 = (const float*)d_in[3];
    const float* w2 = (const float*)d_in[4];
    const float* b2 = (const float*)d_in[5];
    float* out = (float*)d_out;

    void *p_w1t, *p_w2t;
    cudaGetSymbolAddress(&p_w1t, g_w1t);
    cudaGetSymbolAddress(&p_w2t, g_w2t);

    cudaFuncSetAttribute(gemm1_hk, cudaFuncAttributeMaxDynamicSharedMemorySize, SMEM_BYTES);
    cudaFuncSetAttribute(gemm2_hk, cudaFuncAttributeMaxDynamicSharedMemorySize, SMEM_BYTES);

    k_cvt_half<<<2048, 256>>>(x);
    k_transpose_h<<<dim3(TWOD_ / 32, H_ / 64, E_), dim3(32, 8)>>>(w1, (__half*)p_w1t, H_, TWOD_);
    k_transpose_h<<<dim3(H_ / 32, D_ / 64, E_), dim3(32, 8)>>>(w2, (__half*)p_w2t, D_, H_);

    gemm1_hk<<<dim3(T_ / BM, TWOD_ / BN, E_), 256, SMEM_BYTES>>>(b1, rw);
    gemm2_hk<<<dim3(T_ / BM, (H_ + BN - 1) / BN, SPLITK), 256, SMEM_BYTES>>>();
    k_reduce<<<(int)((size_t)T_ * H_ / 8 / 256), 256>>>(rw, b2, out);
}